// round 12
// baseline (speedup 1.0000x reference)
#include <cuda_runtime.h>

#define NXc 64
#define NYc 64
#define NSPOTS 64
#define Pc 6
#define TPB 512          // 16 warps per image

__global__ __launch_bounds__(TPB) void spot_render_kernel(
    const float* __restrict__ z, float* __restrict__ out)
{
    __shared__ float img[NXc * NYc];     // 16 KB, rotate-6 swizzled rows
    __shared__ float slx[NSPOTS * Pc];   // 500 * dx * valid
    __shared__ float sly[NSPOTS * Pc];   // 0.5 * dy * valid
    __shared__ int   smeta[NSPOTS];      // r0 | K<<6 | valid<<12

    const int b    = blockIdx.x;
    const int tid  = threadIdx.x;
    const int lane = tid & 31;
    const int w    = tid >> 5;

    const float inv_alpha = 1.0f / (1.41421356237f * 0.92f);

    // ---- prologue, ONE sync ----
    // threads 0-255: 256 half-items (s,d,h): 4 erfs -> 3 lambda diffs (+ meta on d==0,h==0)
    // threads 256-511: zero the 16 KB image
    if (tid < 256) {
        const int it = tid & 127;
        const int h  = tid >> 7;                 // 0: j=0..3 -> diffs 0..2 ; 1: j=3..6 -> diffs 3..5
        const int s  = it & 63;
        const int d  = it >> 6;                  // 0 = x, 1 = y
        const float* zrow = z + (size_t)b * (2 * NSPOTS);
        const float x0 = __ldg(zrow + s);
        const float y0 = __ldg(zrow + NSPOTS + s);
        const int px = __float2int_rn(x0) - 3;   // round-half-even == jnp.round
        const int py = __float2int_rn(y0) - 3;
        const bool valid = (px >= 0) & (px < NXc - Pc) & (py >= 0) & (py < NYc - Pc);

        if ((d | h) == 0) {
            const int r0 = valid ? px : 0;
            const int c0 = valid ? py : 0;
            const int K  = (c0 + 6 * r0) & 63;
            smeta[s] = r0 | (K << 6) | ((int)valid << 12);
        }

        const float t0 = d ? (y0 - (float)py) : (x0 - (float)px);
        const float scale = (d ? 0.5f : 500.0f) * (valid ? 1.0f : 0.0f);
        const int jb = h * 3;
        const float e0 = erff(((float)(jb + 0) - 0.5f - t0) * inv_alpha);
        const float e1 = erff(((float)(jb + 1) - 0.5f - t0) * inv_alpha);
        const float e2 = erff(((float)(jb + 2) - 0.5f - t0) * inv_alpha);
        const float e3 = erff(((float)(jb + 3) - 0.5f - t0) * inv_alpha);
        float* dst = (d ? sly : slx) + s * Pc + jb;
        dst[0] = (e1 - e0) * scale;
        dst[1] = (e2 - e1) * scale;
        dst[2] = (e3 - e2) * scale;
    } else {
        float4* im4 = reinterpret_cast<float4*>(img);
        const int i = tid - 256;                 // 0..255, 1024 float4 total
        #pragma unroll
        for (int k = 0; k < 4; k++)
            im4[k * 256 + i] = make_float4(0.f, 0.f, 0.f, 0.f);
    }
    __syncthreads();

    // ---- phase C: 4 spots per warp, conflict-free rotate-6 atomics ----
    // pixel p = 6*ix + iy; addr = (r0+ix)*64 + ((K + p) & 63); bank = (K+p) mod 32
    const int p  = lane;
    const int ix = (p * 171) >> 10;              // p/6 for p <= 35
    const int iy = p - ix * Pc;
    #pragma unroll
    for (int k = 0; k < 4; k++) {
        const int s    = w * 4 + k;
        const int meta = smeta[s];               // broadcast
        if (meta >> 12) {                        // warp-uniform: skip invalid spots
            const int r0 = meta & 63;
            const int K  = (meta >> 6) & 63;
            const float v = slx[s * Pc + ix] * sly[s * Pc + iy];
            atomicAdd(&img[((r0 + ix) << 6) + ((K + p) & 63)], v);
        }
    }
    // batched residuals: pixels 32..35 (ix=5, iy=2..5) of this warp's 4 spots, lanes 0-15
    if (lane < 16) {
        const int s2   = w * 4 + (lane >> 2);
        const int p2   = 32 + (lane & 3);
        const int meta = smeta[s2];
        if (meta >> 12) {
            const int r0 = meta & 63;
            const int K  = (meta >> 6) & 63;
            const float v = slx[s2 * Pc + 5] * sly[s2 * Pc + (p2 - 30)];
            atomicAdd(&img[((r0 + 5) << 6) + ((K + p2) & 63)], v);
        }
    }
    __syncthreads();

    // ---- phase D: un-swizzle, fuse 2x LDS.64 -> STG.128 ----
    float4* o4 = reinterpret_cast<float4*>(out + (size_t)b * (NXc * NYc));
    const float2* im2 = reinterpret_cast<const float2*>(img);
    #pragma unroll
    for (int k = 0; k < 2; k++) {
        const int i   = k * TPB + tid;           // float4 index 0..1023
        const int r   = i >> 4;                  // warp-uniform
        const int cg4 = i & 15;
        const float2 a = im2[(r << 5) + (((cg4 << 1)     + 3 * r) & 31)];
        const float2 c = im2[(r << 5) + (((cg4 << 1) + 1 + 3 * r) & 31)];
        o4[i] = make_float4(a.x, a.y, c.x, c.y);
    }
}

extern "C" void kernel_launch(void* const* d_in, const int* in_sizes, int n_in,
                              void* d_out, int out_size)
{
    const float* z = (const float*)d_in[0];
    float* out = (float*)d_out;
    const int B = in_sizes[0] / (2 * NSPOTS);   // 8192
    spot_render_kernel<<<B, TPB>>>(z, out);
}

// round 13
// speedup vs baseline: 1.2517x; 1.2517x over previous
#include <cuda_runtime.h>

#define NXc 64
#define NYc 64
#define NSPOTS 64
#define Pc 6
#define TPB 256
#define RS  70                  // shared image row stride (70 mod 32 = 6 -> conflict-free)
#define IMG_FLOATS (NXc * RS)   // 4480

__global__ __launch_bounds__(TPB) void spot_render_kernel(
    const float* __restrict__ z, float* __restrict__ out)
{
    __shared__ float img[IMG_FLOATS];    // 17.5 KB, stride-70 rows, linear columns
    __shared__ float slx[NSPOTS * Pc];   // 500 * dx * valid
    __shared__ float sly[NSPOTS * Pc];   // 0.5 * dy * valid
    __shared__ int   smeta[NSPOTS];      // base(70*r0+c0) | valid<<13

    const int b    = blockIdx.x;
    const int tid  = threadIdx.x;
    const int lane = tid & 31;
    const int w    = tid >> 5;

    const float inv_alpha = 1.0f / (1.41421356237f * 0.92f);

    // ---- balanced prologue, ONE sync ----
    // every thread: zero a chunk of the image AND compute one erf half-item
    {
        float4* im4 = reinterpret_cast<float4*>(img);    // 1120 float4
        #pragma unroll
        for (int k = 0; k < 4; k++)
            im4[k * TPB + tid] = make_float4(0.f, 0.f, 0.f, 0.f);
        if (tid < IMG_FLOATS / 4 - 4 * TPB)              // 96 extras
            im4[4 * TPB + tid] = make_float4(0.f, 0.f, 0.f, 0.f);
    }
    {
        const int it = tid & 127;                // (s, d) item
        const int h  = tid >> 7;                 // half: j = 3h..3h+3
        const int s  = it & 63;
        const int d  = it >> 6;                  // 0 = x, 1 = y
        const float* zrow = z + (size_t)b * (2 * NSPOTS);
        const float x0 = __ldg(zrow + s);
        const float y0 = __ldg(zrow + NSPOTS + s);
        const int px = __float2int_rn(x0) - 3;   // round-half-even == jnp.round
        const int py = __float2int_rn(y0) - 3;
        const bool valid = (px >= 0) & (px < NXc - Pc) & (py >= 0) & (py < NYc - Pc);

        if ((d | h) == 0) {
            const int base = valid ? (RS * px + py) : 0;
            smeta[s] = base | ((int)valid << 13);
        }

        const float t0 = d ? (y0 - (float)py) : (x0 - (float)px);
        const float scale = (d ? 0.5f : 500.0f) * (valid ? 1.0f : 0.0f);
        const int jb = h * 3;
        const float e0 = erff(((float)(jb + 0) - 0.5f - t0) * inv_alpha);
        const float e1 = erff(((float)(jb + 1) - 0.5f - t0) * inv_alpha);
        const float e2 = erff(((float)(jb + 2) - 0.5f - t0) * inv_alpha);
        const float e3 = erff(((float)(jb + 3) - 0.5f - t0) * inv_alpha);
        float* dst = (d ? sly : slx) + s * Pc + jb;
        dst[0] = (e1 - e0) * scale;
        dst[1] = (e2 - e1) * scale;
        dst[2] = (e3 - e2) * scale;
    }
    __syncthreads();

    // ---- phase C: 8 spots per warp; addr = base + (p + 64*ix), bank=(base+p)%32 ----
    const int p    = lane;
    const int ix   = (p * 171) >> 10;            // p/6 for p <= 35
    const int iy   = p - ix * Pc;
    const int loff = p + 64 * ix;                // per-lane constant offset
    #pragma unroll
    for (int k = 0; k < 8; k++) {
        const int s    = w * 8 + k;
        const int meta = smeta[s];               // broadcast
        if (meta >> 13) {                        // warp-uniform: skip invalid spots
            const float v = slx[s * Pc + ix] * sly[s * Pc + iy];
            atomicAdd(&img[(meta & 8191) + loff], v);
        }
    }
    // batched residuals: pixels 32..35 (ix=5, iy=2..5) of 8 spots in ONE atomic
    {
        const int s2   = w * 8 + (lane >> 2);
        const int meta = smeta[s2];
        if (meta >> 13) {
            const float v = slx[s2 * Pc + 5] * sly[s2 * Pc + 2 + (lane & 3)];
            atomicAdd(&img[(meta & 8191) + 352 + (lane & 3)], v);
        }
    }
    __syncthreads();

    // ---- phase D: linear LDS.64 + coalesced float2 STG ----
    float2* o2 = reinterpret_cast<float2*>(out + (size_t)b * (NXc * NYc));
    #pragma unroll
    for (int k = 0; k < 8; k++) {
        const int i  = k * TPB + tid;            // float2 cell 0..2047
        const int r  = i >> 5;                   // warp-uniform
        const int c2 = i & 31;
        o2[i] = *reinterpret_cast<const float2*>(&img[RS * r + 2 * c2]);
    }
}

extern "C" void kernel_launch(void* const* d_in, const int* in_sizes, int n_in,
                              void* d_out, int out_size)
{
    const float* z = (const float*)d_in[0];
    float* out = (float*)d_out;
    const int B = in_sizes[0] / (2 * NSPOTS);   // 8192
    spot_render_kernel<<<B, TPB>>>(z, out);
}